// round 1
// baseline (speedup 1.0000x reference)
#include <cuda_runtime.h>
#include <cstdint>

typedef unsigned long long ull;

#define NN    256
#define NPIX  65536
#define CIN   192
#define COUT  192

// ---------------- device scratch (no allocations allowed) ----------------
__device__ float g_x[CIN * NPIX];        // planar effective input (48 MB)
__device__ float g_W[COUT * CIN * 9];    // folded weights [OC][IC][tap]
__device__ float g_meanin[CIN];
__device__ float g_add[COUT];            // per-OC additive constant (bias / mean-bias)

// ---------------- f32x2 helpers ----------------
__device__ __forceinline__ void fma2(ull &d, ull a, ull b) {
    asm("fma.rn.f32x2 %0, %1, %2, %0;" : "+l"(d) : "l"(a), "l"(b));
}
__device__ __forceinline__ ull pk(float lo, float hi) {
    ull r; asm("mov.b64 %0, {%1, %2};" : "=l"(r) : "f"(lo), "f"(hi)); return r;
}
__device__ __forceinline__ float2 unpk(ull v) {
    float2 r; asm("mov.b64 {%0, %1}, %2;" : "=f"(r.x), "=f"(r.y) : "l"(v)); return r;
}

// ---------------- weight synthesis: W[OC][IC][9] ----------------
__global__ void k_weights(const float* __restrict__ fil0, const float* __restrict__ fil1,
                          const float* __restrict__ fil2, const float* __restrict__ w00,
                          const float* __restrict__ w01, const float* __restrict__ w10,
                          const float* __restrict__ w11) {
    int idx = blockIdx.x * blockDim.x + threadIdx.x;
    if (idx >= COUT * CIN) return;
    int OC = idx / CIN, IC = idx % CIN;
    float acc[9];
#pragma unroll
    for (int t = 0; t < 9; t++) acc[t] = 0.f;

    if (OC < 64) {
        if (IC < 64) {
            for (int k = 0; k < 3; k++) {
                float c = w00[(OC * 64 + IC) * 3 + k];
#pragma unroll
                for (int t = 0; t < 9; t++) acc[t] += c * fil0[k * 9 + t];
            }
        } else {
            int ici = (IC - 64) >> 1, tin = (IC - 64) & 1;
            for (int k = 0; k < 6; k++) {
                float c = w10[(OC * 64 + ici) * 6 + k];
#pragma unroll
                for (int t = 0; t < 9; t++) acc[t] += c * fil1[(k * 9 + t) * 2 + tin];
            }
        }
    } else {
        int oco = (OC - 64) >> 1, tout = (OC - 64) & 1;
        if (IC < 64) {
            for (int k = 0; k < 6; k++) {
                float c = w01[(oco * 64 + IC) * 6 + k];
#pragma unroll
                for (int t = 0; t < 9; t++) acc[t] += c * fil1[(k * 9 + t) * 2 + tout];
            }
        } else {
            int ici = (IC - 64) >> 1, tin = (IC - 64) & 1;
            for (int k = 0; k < 12; k++) {
                float c = w11[(oco * 64 + ici) * 12 + k];
#pragma unroll
                for (int t = 0; t < 9; t++) acc[t] += c * fil2[((k * 9 + t) * 2 + tin) * 2 + tout];
            }
        }
    }
#pragma unroll
    for (int t = 0; t < 9; t++) g_W[idx * 9 + t] = acc[t];
}

// ---------------- input fold: (x0 | x1 interleaved) -> planar 192 planes ----------------
__global__ void k_fold(const float* __restrict__ x0, const float* __restrict__ x1) {
    int idx = blockIdx.x * blockDim.x + threadIdx.x;   // grid covers CIN*NPIX exactly
    if (idx < 64 * NPIX) {
        g_x[idx] = x0[idx];
    } else {
        int j = idx - 64 * NPIX;
        int plane = j >> 16;         // 0..127
        int p = j & 65535;
        g_x[idx] = x1[(((plane >> 1) << 16) + p) * 2 + (plane & 1)];
    }
}

// ---------------- channel means ----------------
__global__ void k_means() {
    __shared__ float sm[256];
    int ch = blockIdx.x;
    const float* p = g_x + (size_t)ch * NPIX;
    float s = 0.f;
    for (int i = threadIdx.x; i < NPIX; i += 256) s += p[i];
    sm[threadIdx.x] = s;
    __syncthreads();
    for (int o = 128; o > 0; o >>= 1) {
        if (threadIdx.x < o) sm[threadIdx.x] += sm[threadIdx.x + o];
        __syncthreads();
    }
    if (threadIdx.x == 0) g_meanin[ch] = sm[0] * (1.f / NPIX);
}

// ---------------- per-OC additive constant ----------------
// out0: plain bias b0.  out1: mean(conv) * b1, and on a torus
// mean(conv(x,W)) = sum_IC ( sum_tap W[OC,IC,tap] ) * mean(x[IC]).
__global__ void k_addconst(const float* __restrict__ b0, const float* __restrict__ b1) {
    int OC = threadIdx.x;
    if (OC >= COUT) return;
    if (OC < 64) { g_add[OC] = b0[OC]; return; }
    float s = 0.f;
    for (int IC = 0; IC < CIN; IC++) {
        float ws = 0.f;
        const float* w = &g_W[(OC * CIN + IC) * 9];
#pragma unroll
        for (int t = 0; t < 9; t++) ws += w[t];
        s += ws * g_meanin[IC];
    }
    g_add[OC] = s * b1[(OC - 64) >> 1];
}

// ---------------- main conv: 192->192, 3x3, torus, f32x2 ----------------
// block = 128 threads (16x8), tile = 32x16 pixels x 16 out channels.
// Each thread: 2x2 pixel patch; f32x2 packs the two pixels of a row.
#define TIW 36   // smem row stride (even -> float2-aligned), 34 used
__global__ __launch_bounds__(128) void k_conv(float* __restrict__ out) {
    __shared__ float  s_in[18 * TIW];
    __shared__ float2 s_w2[16 * 9];

    int tid = threadIdx.x;
    int tx = tid & 15, ty = tid >> 4;
    int gx0 = blockIdx.x * 32, gy0 = blockIdx.y * 16;
    int ocb = blockIdx.z * 16;

    ull acc[16][2];
#pragma unroll
    for (int o = 0; o < 16; o++) { acc[o][0] = 0ULL; acc[o][1] = 0ULL; }

    for (int ic = 0; ic < CIN; ic++) {
        const float* plane = g_x + (size_t)ic * NPIX;
        // input tile (18 rows x 34 cols), wrap via &255
        for (int i = tid; i < 18 * TIW; i += 128) {
            int r = i / TIW, c = i - r * TIW;
            if (c < 34)
                s_in[i] = plane[((gy0 + r - 1) & 255) * NN + ((gx0 + c - 1) & 255)];
        }
        // weights for this ic, duplicated (w,w) for f32x2
        for (int i = tid; i < 144; i += 128) {
            float w = g_W[((ocb + i / 9) * CIN + ic) * 9 + (i % 9)];
            s_w2[i] = make_float2(w, w);
        }
        __syncthreads();

        // 4x4 patch -> packed horizontal pairs pr[row][shift]
        ull pr[4][3];
        int base = (2 * ty) * TIW + 2 * tx;
#pragma unroll
        for (int r = 0; r < 4; r++) {
            float2 u = *(const float2*)&s_in[base + r * TIW];
            float2 v = *(const float2*)&s_in[base + r * TIW + 2];
            pr[r][0] = pk(u.x, u.y);
            pr[r][1] = pk(u.y, v.x);
            pr[r][2] = pk(v.x, v.y);
        }
#pragma unroll
        for (int oc = 0; oc < 16; oc++) {
#pragma unroll
            for (int ky = 0; ky < 3; ky++) {
#pragma unroll
                for (int kx = 0; kx < 3; kx++) {
                    ull w2 = *(const ull*)&s_w2[oc * 9 + ky * 3 + kx];
                    fma2(acc[oc][0], w2, pr[ky][kx]);       // pixel row Y0
                    fma2(acc[oc][1], w2, pr[ky + 1][kx]);   // pixel row Y0+1
                }
            }
        }
        __syncthreads();
    }

    // epilogue: add per-OC constant, write to the layout the harness expects
    int X0 = gx0 + 2 * tx, Y0 = gy0 + 2 * ty;
    if (ocb < 64) {
        // out0: (oc, y, x)
#pragma unroll
        for (int oc = 0; oc < 16; oc++) {
            int OC = ocb + oc;
            float a = g_add[OC];
            float2 r0 = unpk(acc[oc][0]);
            float2 r1 = unpk(acc[oc][1]);
            r0.x += a; r0.y += a; r1.x += a; r1.y += a;
            *(float2*)&out[(size_t)OC * NPIX + Y0 * NN + X0] = r0;
            *(float2*)&out[(size_t)OC * NPIX + (Y0 + 1) * NN + X0] = r1;
        }
    } else {
        // out1: (oco, y, x, t) with t = (OC-64)&1, oco = (OC-64)>>1
#pragma unroll
        for (int o2 = 0; o2 < 8; o2++) {
            int OCa = ocb + 2 * o2;
            int oco = (OCa - 64) >> 1;
            float aa = g_add[OCa], ab = g_add[OCa + 1];
            float2 a0 = unpk(acc[2 * o2][0]);     // t=0, row Y0, pixels (X0, X0+1)
            float2 a1 = unpk(acc[2 * o2][1]);     // t=0, row Y0+1
            float2 b0 = unpk(acc[2 * o2 + 1][0]); // t=1, row Y0
            float2 b1 = unpk(acc[2 * o2 + 1][1]); // t=1, row Y0+1
            size_t base0 = (size_t)64 * NPIX + ((size_t)(oco * NN + Y0) * NN + X0) * 2;
            size_t base1 = (size_t)64 * NPIX + ((size_t)(oco * NN + Y0 + 1) * NN + X0) * 2;
            float4 v0 = make_float4(a0.x + aa, b0.x + ab, a0.y + aa, b0.y + ab);
            float4 v1 = make_float4(a1.x + aa, b1.x + ab, a1.y + aa, b1.y + ab);
            *(float4*)&out[base0] = v0;
            *(float4*)&out[base1] = v1;
        }
    }
}

// ---------------- launcher ----------------
extern "C" void kernel_launch(void* const* d_in, const int* in_sizes, int n_in,
                              void* d_out, int out_size) {
    const float* x0   = (const float*)d_in[0];
    const float* x1   = (const float*)d_in[1];
    const float* fil0 = (const float*)d_in[2];
    const float* fil1 = (const float*)d_in[3];
    const float* fil2 = (const float*)d_in[4];
    const float* w00  = (const float*)d_in[5];
    const float* w01  = (const float*)d_in[6];
    const float* w10  = (const float*)d_in[7];
    const float* w11  = (const float*)d_in[8];
    const float* b0   = (const float*)d_in[9];
    const float* b1   = (const float*)d_in[10];
    float* out = (float*)d_out;

    k_weights<<<(COUT * CIN + 255) / 256, 256>>>(fil0, fil1, fil2, w00, w01, w10, w11);
    k_fold<<<(CIN * NPIX) / 256, 256>>>(x0, x1);
    k_means<<<CIN, 256>>>();
    k_addconst<<<1, 256>>>(b0, b1);

    dim3 grid(NN / 32, NN / 16, COUT / 16);
    k_conv<<<grid, 128>>>(out);
}

// round 3
// speedup vs baseline: 4.2806x; 4.2806x over previous
#include <cuda_runtime.h>
#include <cuda_bf16.h>
#include <cstdint>

#define NN     256
#define NPIX   65536
#define CIN    192
#define COUT   192
#define NCHUNK 27              // 9 taps x 3 ic-chunks of 64
#define TILE_BF16  12288       // 192 rows x 64 bf16 (one B tile)
#define B_CHUNK_BYTES 49152    // hi + lo B tiles
#define STAGE_BYTES 81920      // A_hi 16K + A_lo 16K + B 48K, 1KB aligned

// ---------------- device scratch ----------------
__device__ float g_W[COUT * CIN * 9];
__device__ float g_meanin[CIN];
__device__ float g_add[COUT];
__device__ __align__(1024) __nv_bfloat16 g_Wbf[(size_t)NCHUNK * 2 * TILE_BF16];
__device__ uint32_t g_xp[(size_t)CIN * NPIX];   // packed (hi bf16 | lo bf16 << 16)

// ---------------- helpers ----------------
__device__ __forceinline__ uint32_t smem_u32(const void* p) {
    uint32_t a;
    asm("{ .reg .u64 t; cvta.to.shared.u64 t, %1; cvt.u32.u64 %0, t; }" : "=r"(a) : "l"(p));
    return a;
}
__device__ __forceinline__ uint32_t swz(uint32_t off) { return off ^ ((off >> 3) & 0x70); }
__device__ __forceinline__ void ldsm4(uint32_t* r, uint32_t addr) {
    asm volatile("ldmatrix.sync.aligned.m8n8.x4.shared.b16 {%0,%1,%2,%3}, [%4];"
                 : "=r"(r[0]), "=r"(r[1]), "=r"(r[2]), "=r"(r[3]) : "r"(addr));
}
__device__ __forceinline__ void mma16816(float* d, const uint32_t* a, const uint32_t* b) {
    asm volatile("mma.sync.aligned.m16n8k16.row.col.f32.bf16.bf16.f32 "
                 "{%0,%1,%2,%3}, {%4,%5,%6,%7}, {%8,%9}, {%0,%1,%2,%3};"
                 : "+f"(d[0]), "+f"(d[1]), "+f"(d[2]), "+f"(d[3])
                 : "r"(a[0]), "r"(a[1]), "r"(a[2]), "r"(a[3]), "r"(b[0]), "r"(b[1]));
}
__device__ __forceinline__ void cpa16(uint32_t dst, const void* src) {
    asm volatile("cp.async.cg.shared.global [%0], [%1], 16;" :: "r"(dst), "l"(src));
}

// ---------------- weight synthesis: fp32 W[OC][IC][9] ----------------
__global__ void k_weights(const float* __restrict__ fil0, const float* __restrict__ fil1,
                          const float* __restrict__ fil2, const float* __restrict__ w00,
                          const float* __restrict__ w01, const float* __restrict__ w10,
                          const float* __restrict__ w11) {
    int idx = blockIdx.x * blockDim.x + threadIdx.x;
    if (idx >= COUT * CIN) return;
    int OC = idx / CIN, IC = idx % CIN;
    float acc[9];
#pragma unroll
    for (int t = 0; t < 9; t++) acc[t] = 0.f;
    if (OC < 64) {
        if (IC < 64) {
            for (int k = 0; k < 3; k++) {
                float c = w00[(OC * 64 + IC) * 3 + k];
#pragma unroll
                for (int t = 0; t < 9; t++) acc[t] += c * fil0[k * 9 + t];
            }
        } else {
            int ici = (IC - 64) >> 1, tin = (IC - 64) & 1;
            for (int k = 0; k < 6; k++) {
                float c = w10[(OC * 64 + ici) * 6 + k];
#pragma unroll
                for (int t = 0; t < 9; t++) acc[t] += c * fil1[(k * 9 + t) * 2 + tin];
            }
        }
    } else {
        int oco = (OC - 64) >> 1, tout = (OC - 64) & 1;
        if (IC < 64) {
            for (int k = 0; k < 6; k++) {
                float c = w01[(oco * 64 + IC) * 6 + k];
#pragma unroll
                for (int t = 0; t < 9; t++) acc[t] += c * fil1[(k * 9 + t) * 2 + tout];
            }
        } else {
            int ici = (IC - 64) >> 1, tin = (IC - 64) & 1;
            for (int k = 0; k < 12; k++) {
                float c = w11[(oco * 64 + ici) * 12 + k];
#pragma unroll
                for (int t = 0; t < 9; t++) acc[t] += c * fil2[((k * 9 + t) * 2 + tin) * 2 + tout];
            }
        }
    }
#pragma unroll
    for (int t = 0; t < 9; t++) g_W[idx * 9 + t] = acc[t];
}

// ---------------- W -> bf16 hi/lo, pre-swizzled SW128 [n][k] tiles ----------------
__global__ void k_wsplit() {
    int n = blockIdx.y;            // OC row
    int tile = blockIdx.x;         // tap*3 + icgroup
    int k = threadIdx.x;           // 0..63
    int tap = tile / 3, c = tile % 3;
    int ic = c * 64 + k;
    float v = g_W[(n * CIN + ic) * 9 + tap];
    __nv_bfloat16 h = __float2bfloat16(v);
    float r = v - __bfloat162float(h);
    __nv_bfloat16 l = __float2bfloat16(r);
    uint32_t sw = swz((uint32_t)(n * 128 + k * 2));
    size_t base = (size_t)tile * 2 * TILE_BF16;
    g_Wbf[base + (sw >> 1)] = h;
    g_Wbf[base + TILE_BF16 + (sw >> 1)] = l;
}

// ---------------- x -> packed (hi|lo) planes, 192 effective channels ----------------
__global__ void k_xpack(const float* __restrict__ x0, const float* __restrict__ x1) {
    int idx = blockIdx.x * 256 + threadIdx.x;
    int ch = idx >> 16, pix = idx & 65535;
    float v;
    if (ch < 64) v = x0[idx];
    else {
        int j = ch - 64;
        v = x1[((size_t)(j >> 1) * NPIX + pix) * 2 + (j & 1)];
    }
    __nv_bfloat16 h = __float2bfloat16(v);
    float r = v - __bfloat162float(h);
    __nv_bfloat16 l = __float2bfloat16(r);
    g_xp[idx] = (uint32_t)__bfloat16_as_ushort(h) | ((uint32_t)__bfloat16_as_ushort(l) << 16);
}

// ---------------- channel means ----------------
__global__ void k_means(const float* __restrict__ x0, const float* __restrict__ x1) {
    __shared__ float sm[256];
    int ch = blockIdx.x;
    float s = 0.f;
    if (ch < 64) {
        const float* p = x0 + (size_t)ch * NPIX;
        for (int i = threadIdx.x; i < NPIX; i += 256) s += p[i];
    } else {
        int j = ch - 64;
        const float* p = x1 + (size_t)(j >> 1) * (2 * NPIX) + (j & 1);
        for (int i = threadIdx.x; i < NPIX; i += 256) s += p[2 * i];
    }
    sm[threadIdx.x] = s;
    __syncthreads();
    for (int o = 128; o > 0; o >>= 1) {
        if (threadIdx.x < o) sm[threadIdx.x] += sm[threadIdx.x + o];
        __syncthreads();
    }
    if (threadIdx.x == 0) g_meanin[ch] = sm[0] * (1.f / NPIX);
}

// ---------------- per-OC additive constant ----------------
__global__ void k_addconst(const float* __restrict__ b0, const float* __restrict__ b1) {
    __shared__ float sm[256];
    int OC = blockIdx.x, tid = threadIdx.x;
    float s = 0.f;
    if (tid < CIN) {
        const float* w = &g_W[(OC * CIN + tid) * 9];
        float ws = 0.f;
#pragma unroll
        for (int t = 0; t < 9; t++) ws += w[t];
        s = ws * g_meanin[tid];
    }
    sm[tid] = s;
    __syncthreads();
    for (int o = 128; o > 0; o >>= 1) {
        if (tid < o) sm[tid] += sm[tid + o];
        __syncthreads();
    }
    if (tid == 0) g_add[OC] = (OC < 64) ? b0[OC] : sm[0] * b1[(OC - 64) >> 1];
}

// ---------------- main conv: implicit GEMM on mma.sync (HMMA bf16) ----------------
// CTA 256 thr = 8 warps (4 M x 2 N). M=128 px, N=192 OC, K=27x64.
// 3-MMA bf16 split: hi*hi + lo*hi + hi*lo, fp32 accum.
__global__ __launch_bounds__(256) void k_conv(float* __restrict__ out) {
    extern __shared__ __align__(1024) char smem[];
    const uint32_t sb = smem_u32(smem);
    const int tid = threadIdx.x;
    const int lane = tid & 31, warp = tid >> 5;
    const int wm = warp & 3, wn = warp >> 2;
    const int bid = blockIdx.x;
    const int y = bid >> 1, xb = (bid & 1) << 7;

    // ldmatrix lane geometry
    const int a_row = (lane & 7) + ((lane >> 3) & 1) * 8;  // within m16 tile
    const int a_ks  = (lane >> 4);                          // k half (0/1)
    const int b_row = (lane & 7) + ((lane >> 4) << 3);      // within n16 group
    const int b_ks  = (lane >> 3) & 1;

    float acc[2][12][4];
#pragma unroll
    for (int t = 0; t < 2; t++)
#pragma unroll
        for (int n = 0; n < 12; n++)
#pragma unroll
            for (int q = 0; q < 4; q++) acc[t][n][q] = 0.f;

    uint32_t ra[16], rb[16];

    // ---- per-chunk helpers (macros keep everything unrolled/register-resident) ----
#define PREFETCH(I)                                                              \
    {                                                                            \
        int tap = (I) / 3, c = (I) % 3;                                          \
        int ky = tap / 3, kx = tap % 3;                                          \
        int gy = (y + ky + 255) & 255;                                           \
        int pixoff[2];                                                           \
        _Pragma("unroll")                                                        \
        for (int mb = 0; mb < 2; mb++) {                                         \
            int m = warp * 16 + mb * 8 + (lane & 7);                             \
            pixoff[mb] = (gy << 8) + ((xb + m + kx + 255) & 255);                \
        }                                                                        \
        _Pragma("unroll")                                                        \
        for (int j = 0; j < 8; j++) {                                            \
            int k2 = (lane >> 3) + 4 * j;                                        \
            size_t chb = ((size_t)(c * 64 + 2 * k2)) << 16;                      \
            _Pragma("unroll")                                                    \
            for (int mb = 0; mb < 2; mb++) {                                     \
                ra[j * 2 + mb] = g_xp[chb + pixoff[mb]];                         \
                rb[j * 2 + mb] = g_xp[chb + NPIX + pixoff[mb]];                  \
            }                                                                    \
        }                                                                        \
    }

#define STORE_A(S)                                                               \
    {                                                                            \
        char* Ah = smem + (S) * STAGE_BYTES;                                     \
        _Pragma("unroll")                                                        \
        for (int j = 0; j < 8; j++) {                                            \
            int k2 = (lane >> 3) + 4 * j;                                        \
            _Pragma("unroll")                                                    \
            for (int mb = 0; mb < 2; mb++) {                                     \
                int m = warp * 16 + mb * 8 + (lane & 7);                         \
                uint32_t a = ra[j * 2 + mb], b = rb[j * 2 + mb];                 \
                uint32_t hi = __byte_perm(a, b, 0x5410);                         \
                uint32_t lo = __byte_perm(a, b, 0x7632);                         \
                uint32_t sw = swz((uint32_t)(m * 128 + k2 * 4));                 \
                *(uint32_t*)(Ah + sw) = hi;                                      \
                *(uint32_t*)(Ah + 16384 + sw) = lo;                              \
            }                                                                    \
        }                                                                        \
    }

#define CPB(I, S)                                                                \
    {                                                                            \
        const char* src = (const char*)(g_Wbf + (size_t)(I) * 2 * TILE_BF16);    \
        uint32_t dst = sb + (S) * STAGE_BYTES + 32768;                           \
        _Pragma("unroll")                                                        \
        for (int j = 0; j < 12; j++) {                                           \
            int off = (tid + 256 * j) * 16;                                      \
            cpa16(dst + off, src + off);                                         \
        }                                                                        \
    }

    // ---- pipeline head ----
    PREFETCH(0);
    CPB(0, 0);
    asm volatile("cp.async.commit_group;");
    STORE_A(0);
    asm volatile("cp.async.wait_group 0;");
    __syncthreads();

    for (int i = 0; i < NCHUNK; i++) {
        const int cur = i & 1;
        if (i < NCHUNK - 1) {
            PREFETCH(i + 1);
            CPB(i + 1, cur ^ 1);
            asm volatile("cp.async.commit_group;");
        }

        // ---- MMA on stage cur ----
        {
            const uint32_t Ah = sb + cur * STAGE_BYTES;
            const uint32_t Al = Ah + 16384;
            const uint32_t Bh = Ah + 32768;
            const uint32_t Bl = Ah + 32768 + 24576;
#pragma unroll
            for (int ks = 0; ks < 4; ks++) {
                uint32_t ah[2][4], al[2][4];
#pragma unroll
                for (int t = 0; t < 2; t++) {
                    uint32_t off = swz((uint32_t)((wm * 32 + t * 16 + a_row) * 128 + ks * 32 + a_ks * 16));
                    ldsm4(ah[t], Ah + off);
                    ldsm4(al[t], Al + off);
                }
#pragma unroll
                for (int nn = 0; nn < 6; nn++) {
                    uint32_t offb = swz((uint32_t)((wn * 96 + nn * 16 + b_row) * 128 + ks * 32 + b_ks * 16));
                    uint32_t bh[4], bl[4];
                    ldsm4(bh, Bh + offb);
                    ldsm4(bl, Bl + offb);
#pragma unroll
                    for (int t = 0; t < 2; t++) {
#pragma unroll
                        for (int h = 0; h < 2; h++) {
                            float* d = acc[t][nn * 2 + h];
                            mma16816(d, ah[t], bh + 2 * h);
                            mma16816(d, al[t], bh + 2 * h);
                            mma16816(d, ah[t], bl + 2 * h);
                        }
                    }
                }
            }
        }

        if (i < NCHUNK - 1) {
            STORE_A(cur ^ 1);
            asm volatile("cp.async.wait_group 0;");
            __syncthreads();
        }
    }

    // ---- epilogue ----
    const int col = (lane & 3) * 2;
    const int rowq = lane >> 2;
#pragma unroll
    for (int t = 0; t < 2; t++) {
        int px0 = xb + wm * 32 + t * 16 + rowq;
        int px1 = px0 + 8;
#pragma unroll
        for (int nf = 0; nf < 12; nf++) {
            int n = wn * 96 + nf * 8 + col;
            float g0 = __ldg(&g_add[n]), g1 = __ldg(&g_add[n + 1]);
            float v0 = acc[t][nf][0] + g0, v1 = acc[t][nf][1] + g1;
            float v2 = acc[t][nf][2] + g0, v3 = acc[t][nf][3] + g1;
            if (n < 64) {
                out[(size_t)n * NPIX + y * NN + px0]       = v0;
                out[(size_t)(n + 1) * NPIX + y * NN + px0] = v1;
                out[(size_t)n * NPIX + y * NN + px1]       = v2;
                out[(size_t)(n + 1) * NPIX + y * NN + px1] = v3;
            } else {
                int oco = (n - 64) >> 1;
                size_t base = (size_t)64 * NPIX + ((size_t)(oco * NN + y) * NN) * 2;
                *(float2*)&out[base + px0 * 2] = make_float2(v0, v1);
                *(float2*)&out[base + px1 * 2] = make_float2(v2, v3);
            }
        }
    }
#undef PREFETCH
#undef STORE_A
#undef CPB
}

// ---------------- launcher ----------------
extern "C" void kernel_launch(void* const* d_in, const int* in_sizes, int n_in,
                              void* d_out, int out_size) {
    const float* x0   = (const float*)d_in[0];
    const float* x1   = (const float*)d_in[1];
    const float* fil0 = (const float*)d_in[2];
    const float* fil1 = (const float*)d_in[3];
    const float* fil2 = (const float*)d_in[4];
    const float* w00  = (const float*)d_in[5];
    const float* w01  = (const float*)d_in[6];
    const float* w10  = (const float*)d_in[7];
    const float* w11  = (const float*)d_in[8];
    const float* b0   = (const float*)d_in[9];
    const float* b1   = (const float*)d_in[10];
    float* out = (float*)d_out;

    k_weights<<<(COUT * CIN + 255) / 256, 256>>>(fil0, fil1, fil2, w00, w01, w10, w11);
    k_wsplit<<<dim3(NCHUNK, COUT), 64>>>();
    k_xpack<<<(CIN * NPIX) / 256, 256>>>(x0, x1);
    k_means<<<CIN, 256>>>(x0, x1);
    k_addconst<<<COUT, 256>>>(b0, b1);

    const int dyn_smem = 2 * STAGE_BYTES;  // 163840
    cudaFuncSetAttribute(k_conv, cudaFuncAttributeMaxDynamicSharedMemorySize, dyn_smem);
    k_conv<<<512, 256, dyn_smem>>>(out);
}

// round 5
// speedup vs baseline: 4.9022x; 1.1452x over previous
#include <cuda_runtime.h>
#include <cuda_bf16.h>
#include <cstdint>

#define NN     256
#define NPIX   65536
#define CIN    192
#define COUT   192
#define NCHUNK 27
#define TILE_BF16  12288        // 192 x 64 bf16 (one B tile)
#define STAGE_BYTES 81920       // A_hi 16K | A_lo 16K | B_hi 24K | B_lo 24K

// ---------------- device scratch ----------------
__device__ float g_W[COUT * CIN * 9];
__device__ float g_meanin[CIN];
__device__ float g_add[COUT];
__device__ __align__(1024) __nv_bfloat16 g_Wbf[(size_t)NCHUNK * 2 * TILE_BF16];
__device__ __align__(16) uint32_t g_xh[(size_t)3 * NPIX * 32];  // [c][pix][k2] hi pairs
__device__ __align__(16) uint32_t g_xl[(size_t)3 * NPIX * 32];  // lo pairs

// ---------------- helpers ----------------
__device__ __forceinline__ uint32_t smem_u32(const void* p) {
    uint32_t a;
    asm("{ .reg .u64 t; cvta.to.shared.u64 t, %1; cvt.u32.u64 %0, t; }" : "=r"(a) : "l"(p));
    return a;
}
__device__ __forceinline__ uint32_t swz(uint32_t off) { return off ^ ((off >> 3) & 0x70); }
__device__ __forceinline__ void ldsm4(uint32_t* r, uint32_t addr) {
    asm volatile("ldmatrix.sync.aligned.m8n8.x4.shared.b16 {%0,%1,%2,%3}, [%4];"
                 : "=r"(r[0]), "=r"(r[1]), "=r"(r[2]), "=r"(r[3]) : "r"(addr));
}
__device__ __forceinline__ void mma16816(float* d, const uint32_t* a, const uint32_t* b) {
    asm volatile("mma.sync.aligned.m16n8k16.row.col.f32.bf16.bf16.f32 "
                 "{%0,%1,%2,%3}, {%4,%5,%6,%7}, {%8,%9}, {%0,%1,%2,%3};"
                 : "+f"(d[0]), "+f"(d[1]), "+f"(d[2]), "+f"(d[3])
                 : "r"(a[0]), "r"(a[1]), "r"(a[2]), "r"(a[3]), "r"(b[0]), "r"(b[1]));
}
__device__ __forceinline__ void cpa16(uint32_t dst, const void* src) {
    asm volatile("cp.async.cg.shared.global [%0], [%1], 16;" :: "r"(dst), "l"(src));
}

// ================= launch 0: weight synthesis W[OC][IC][9] =================
__global__ void k_weights(const float* __restrict__ fil0, const float* __restrict__ fil1,
                          const float* __restrict__ fil2, const float* __restrict__ w00,
                          const float* __restrict__ w01, const float* __restrict__ w10,
                          const float* __restrict__ w11) {
    int idx = blockIdx.x * blockDim.x + threadIdx.x;
    if (idx >= COUT * CIN) return;
    int OC = idx / CIN, IC = idx % CIN;
    float acc[9];
#pragma unroll
    for (int t = 0; t < 9; t++) acc[t] = 0.f;
    if (OC < 64) {
        if (IC < 64) {
            for (int k = 0; k < 3; k++) {
                float c = w00[(OC * 64 + IC) * 3 + k];
#pragma unroll
                for (int t = 0; t < 9; t++) acc[t] += c * fil0[k * 9 + t];
            }
        } else {
            int ici = (IC - 64) >> 1, tin = (IC - 64) & 1;
            for (int k = 0; k < 6; k++) {
                float c = w10[(OC * 64 + ici) * 6 + k];
#pragma unroll
                for (int t = 0; t < 9; t++) acc[t] += c * fil1[(k * 9 + t) * 2 + tin];
            }
        }
    } else {
        int oco = (OC - 64) >> 1, tout = (OC - 64) & 1;
        if (IC < 64) {
            for (int k = 0; k < 6; k++) {
                float c = w01[(oco * 64 + IC) * 6 + k];
#pragma unroll
                for (int t = 0; t < 9; t++) acc[t] += c * fil1[(k * 9 + t) * 2 + tout];
            }
        } else {
            int ici = (IC - 64) >> 1, tin = (IC - 64) & 1;
            for (int k = 0; k < 12; k++) {
                float c = w11[(oco * 64 + ici) * 12 + k];
#pragma unroll
                for (int t = 0; t < 9; t++) acc[t] += c * fil2[((k * 9 + t) * 2 + tin) * 2 + tout];
            }
        }
    }
#pragma unroll
    for (int t = 0; t < 9; t++) g_W[idx * 9 + t] = acc[t];
}

// ================= launch 1: x -> pixel-major hi/lo planes + channel means =================
// grid (512, 4) block 128. y<3: pack role (c=y, 128 pixels). y==3: means role (block=channel).
#define XS 36   // smem row stride in words (144 B, 16B-aligned rows)
__global__ void k_xpack(const float* __restrict__ x0, const float* __restrict__ x1) {
    if (blockIdx.y == 3) {
        if (blockIdx.x >= CIN) return;
        __shared__ float sm[128];
        int ch = blockIdx.x;
        float s = 0.f;
        if (ch < 64) {
            const float* p = x0 + (size_t)ch * NPIX;
            for (int i = threadIdx.x; i < NPIX; i += 128) s += p[i];
        } else {
            int j = ch - 64;
            const float* p = x1 + (size_t)(j >> 1) * (2 * NPIX) + (j & 1);
            for (int i = threadIdx.x; i < NPIX; i += 128) s += p[2 * i];
        }
        sm[threadIdx.x] = s;
        __syncthreads();
        for (int o = 64; o > 0; o >>= 1) {
            if (threadIdx.x < o) sm[threadIdx.x] += sm[threadIdx.x + o];
            __syncthreads();
        }
        if (threadIdx.x == 0) g_meanin[ch] = sm[0] * (1.f / NPIX);
        return;
    }
    __shared__ uint32_t shh[128 * XS];
    __shared__ uint32_t shl[128 * XS];
    const int c = blockIdx.y, tid = threadIdx.x;
    const int px = blockIdx.x * 128 + tid;
#pragma unroll 4
    for (int k2 = 0; k2 < 32; k2++) {
        float v0, v1;
        if (c == 0) {
            v0 = x0[(size_t)(2 * k2) * NPIX + px];
            v1 = x0[(size_t)(2 * k2 + 1) * NPIX + px];
        } else {
            int j = (c - 1) * 64 + 2 * k2;           // x1 flat channel (even)
            float2 p = *(const float2*)&x1[((size_t)(j >> 1) * NPIX + px) * 2];
            v0 = p.x; v1 = p.y;
        }
        __nv_bfloat16 h0 = __float2bfloat16(v0), h1 = __float2bfloat16(v1);
        float r0 = v0 - __bfloat162float(h0), r1 = v1 - __bfloat162float(h1);
        __nv_bfloat16 l0 = __float2bfloat16(r0), l1 = __float2bfloat16(r1);
        shh[tid * XS + k2] = (uint32_t)__bfloat16_as_ushort(h0) | ((uint32_t)__bfloat16_as_ushort(h1) << 16);
        shl[tid * XS + k2] = (uint32_t)__bfloat16_as_ushort(l0) | ((uint32_t)__bfloat16_as_ushort(l1) << 16);
    }
    __syncthreads();
    // write 128B rows coalesced: slot s = (px_local, q); row stride 144B keeps uint4 aligned
#pragma unroll
    for (int r = 0; r < 8; r++) {
        int s = tid + 128 * r;
        int pl = s >> 3, q = s & 7;
        uint4 vh = *(const uint4*)&shh[pl * XS + q * 4];
        uint4 vl = *(const uint4*)&shl[pl * XS + q * 4];
        size_t o = ((size_t)c * NPIX + blockIdx.x * 128 + pl) * 32 + q * 4;
        *(uint4*)&g_xh[o] = vh;
        *(uint4*)&g_xl[o] = vl;
    }
}

// ================= launch 2: W split/swizzle + per-OC additive const =================
__global__ void k_wsplit_addconst(const float* __restrict__ b0, const float* __restrict__ b1) {
    int bid = blockIdx.x, tid = threadIdx.x;
    if (bid < NCHUNK * COUT) {
        if (tid >= 64) return;
        int tile = bid % NCHUNK, n = bid / NCHUNK;
        int tap = tile / 3, c = tile % 3;
        int ic = c * 64 + tid;
        float v = g_W[(n * CIN + ic) * 9 + tap];
        __nv_bfloat16 h = __float2bfloat16(v);
        float r = v - __bfloat162float(h);
        __nv_bfloat16 l = __float2bfloat16(r);
        uint32_t sw = swz((uint32_t)(n * 128 + tid * 2));
        size_t base = (size_t)tile * 2 * TILE_BF16;
        g_Wbf[base + (sw >> 1)] = h;
        g_Wbf[base + TILE_BF16 + (sw >> 1)] = l;
        return;
    }
    __shared__ float sm[256];
    int OC = bid - NCHUNK * COUT;
    float s = 0.f;
    if (tid < CIN) {
        const float* w = &g_W[(OC * CIN + tid) * 9];
        float ws = 0.f;
#pragma unroll
        for (int t = 0; t < 9; t++) ws += w[t];
        s = ws * g_meanin[tid];
    }
    sm[tid] = s;
    __syncthreads();
    for (int o = 128; o > 0; o >>= 1) {
        if (tid < o) sm[tid] += sm[tid + o];
        __syncthreads();
    }
    if (tid == 0) g_add[OC] = (OC < 64) ? b0[OC] : sm[0] * b1[(OC - 64) >> 1];
}

// ================= launch 3: conv = implicit GEMM on HMMA =================
// 512 thr = 16 warps (4M x 4N). M=128 px, N=192, K=27x64. 3-term bf16 split.
__global__ __launch_bounds__(512) void k_conv(float* __restrict__ out) {
    extern __shared__ __align__(1024) char smem[];
    const uint32_t sb = smem_u32(smem);
    const int tid = threadIdx.x;
    const int lane = tid & 31, warp = tid >> 5;
    const int wm = warp & 3, wn = warp >> 2;
    const int y = blockIdx.x >> 1, xb = (blockIdx.x & 1) << 7;

    const int a_row = (lane & 7) + ((lane >> 3) & 1) * 8;
    const int a_ks  = lane >> 4;
    const int b_row = (lane & 7) + ((lane >> 4) << 3);
    const int b_ks  = (lane >> 3) & 1;

    const int am = tid >> 2;         // A-row this thread loads (0..127)
    const int aq = (tid & 3) * 2;    // 16B chunk pair (0,2,4,6)

    float acc[2][6][4];
#pragma unroll
    for (int t = 0; t < 2; t++)
#pragma unroll
        for (int g = 0; g < 6; g++)
#pragma unroll
            for (int q = 0; q < 4; q++) acc[t][g][q] = 0.f;

#define ISSUE(I, S)                                                                  \
    {                                                                                \
        int tap = (I) / 3, c = (I) % 3;                                              \
        int ky = tap / 3, kx = tap % 3;                                              \
        int ps = (((y + ky + 255) & 255) << 8) | ((xb + am + kx + 255) & 255);       \
        size_t so = ((size_t)((c << 16) + ps)) * 128 + (size_t)(aq * 16);            \
        uint32_t d0 = sb + (S) * STAGE_BYTES + swz((uint32_t)(am * 128 + aq * 16));  \
        uint32_t d1 = sb + (S) * STAGE_BYTES + swz((uint32_t)(am * 128 + aq * 16 + 16)); \
        cpa16(d0, (const char*)g_xh + so);                                           \
        cpa16(d1, (const char*)g_xh + so + 16);                                      \
        cpa16(d0 + 16384, (const char*)g_xl + so);                                   \
        cpa16(d1 + 16384, (const char*)g_xl + so + 16);                              \
        const char* bsrc = (const char*)g_Wbf + (size_t)(I) * 49152;                 \
        uint32_t dB = sb + (S) * STAGE_BYTES + 32768;                                \
        _Pragma("unroll")                                                            \
        for (int j = 0; j < 6; j++) {                                                \
            int off = (tid + 512 * j) * 16;                                          \
            cpa16(dB + off, bsrc + off);                                             \
        }                                                                            \
        asm volatile("cp.async.commit_group;");                                      \
    }

    ISSUE(0, 0);
    asm volatile("cp.async.wait_group 0;");
    __syncthreads();

    for (int i = 0; i < NCHUNK; i++) {
        const int cur = i & 1;
        if (i < NCHUNK - 1) ISSUE(i + 1, cur ^ 1);

        const uint32_t Ab = sb + cur * STAGE_BYTES;
        const uint32_t Bb = Ab + 32768;
#pragma unroll
        for (int ks = 0; ks < 4; ks++) {
            uint32_t ah[2][4], al[2][4];
#pragma unroll
            for (int t = 0; t < 2; t++) {
                uint32_t off = swz((uint32_t)((wm * 32 + t * 16 + a_row) * 128 + ks * 32 + a_ks * 16));
                ldsm4(ah[t], Ab + off);
                ldsm4(al[t], Ab + 16384 + off);
            }
#pragma unroll
            for (int g = 0; g < 3; g++) {
                uint32_t offb = swz((uint32_t)((wn * 48 + g * 16 + b_row) * 128 + ks * 32 + b_ks * 16));
                uint32_t bh[4], bl[4];
                ldsm4(bh, Bb + offb);
                ldsm4(bl, Bb + 24576 + offb);
#pragma unroll
                for (int t = 0; t < 2; t++) {
#pragma unroll
                    for (int h = 0; h < 2; h++) {
                        float* d = acc[t][g * 2 + h];
                        mma16816(d, ah[t], bh + 2 * h);
                        mma16816(d, al[t], bh + 2 * h);
                        mma16816(d, ah[t], bl + 2 * h);
                    }
                }
            }
        }

        if (i < NCHUNK - 1) {
            asm volatile("cp.async.wait_group 0;");
            __syncthreads();
        }
    }
#undef ISSUE

    // ---- epilogue ----
    const int col = (lane & 3) * 2;
    const int rowq = lane >> 2;
#pragma unroll
    for (int t = 0; t < 2; t++) {
        int px0 = xb + wm * 32 + t * 16 + rowq;
        int px1 = px0 + 8;
#pragma unroll
        for (int nf = 0; nf < 6; nf++) {
            int n = wn * 48 + nf * 8 + col;
            float g0 = __ldg(&g_add[n]), g1 = __ldg(&g_add[n + 1]);
            float v0 = acc[t][nf][0] + g0, v1 = acc[t][nf][1] + g1;
            float v2 = acc[t][nf][2] + g0, v3 = acc[t][nf][3] + g1;
            if (n < 64) {
                out[(size_t)n * NPIX + y * NN + px0]       = v0;
                out[(size_t)(n + 1) * NPIX + y * NN + px0] = v1;
                out[(size_t)n * NPIX + y * NN + px1]       = v2;
                out[(size_t)(n + 1) * NPIX + y * NN + px1] = v3;
            } else {
                int oco = (n - 64) >> 1;
                size_t base = (size_t)64 * NPIX + ((size_t)(oco * NN + y) * NN) * 2;
                *(float2*)&out[base + px0 * 2] = make_float2(v0, v1);
                *(float2*)&out[base + px1 * 2] = make_float2(v2, v3);
            }
        }
    }
}

// ---------------- launcher ----------------
extern "C" void kernel_launch(void* const* d_in, const int* in_sizes, int n_in,
                              void* d_out, int out_size) {
    const float* x0   = (const float*)d_in[0];
    const float* x1   = (const float*)d_in[1];
    const float* fil0 = (const float*)d_in[2];
    const float* fil1 = (const float*)d_in[3];
    const float* fil2 = (const float*)d_in[4];
    const float* w00  = (const float*)d_in[5];
    const float* w01  = (const float*)d_in[6];
    const float* w10  = (const float*)d_in[7];
    const float* w11  = (const float*)d_in[8];
    const float* b0   = (const float*)d_in[9];
    const float* b1   = (const float*)d_in[10];
    float* out = (float*)d_out;

    k_weights<<<(COUT * CIN + 255) / 256, 256>>>(fil0, fil1, fil2, w00, w01, w10, w11);
    k_xpack<<<dim3(512, 4), 128>>>(x0, x1);
    k_wsplit_addconst<<<NCHUNK * COUT + COUT, 256>>>(b0, b1);

    const int dyn_smem = 2 * STAGE_BYTES;  // 163840
    cudaFuncSetAttribute(k_conv, cudaFuncAttributeMaxDynamicSharedMemorySize, dyn_smem);
    k_conv<<<512, 512, dyn_smem>>>(out);
}

// round 6
// speedup vs baseline: 6.1950x; 1.2637x over previous
#include <cuda_runtime.h>
#include <cuda_fp16.h>
#include <cstdint>

#define NN     256
#define NPIX   65536
#define CIN    192
#define COUT   192
#define NCHUNK 27
#define STG    45056          // stage: A_hi 16K | A_lo 16K | B 12K (+pad)

// ---------------- device scratch ----------------
__device__ float g_W[COUT * CIN * 9];
__device__ float g_meanin[CIN];
__device__ float g_add[COUT];
__device__ __align__(1024) __half g_Wh[(size_t)NCHUNK * 2 * 6144];  // [chunk][nh] 96x64 fp16 swizzled
__device__ __align__(16) uint32_t g_xh[(size_t)3 * NPIX * 32];      // [c][pix][k2] fp16 hi pairs
__device__ __align__(16) uint32_t g_xl[(size_t)3 * NPIX * 32];      // fp16 lo pairs

// ---------------- helpers ----------------
__device__ __forceinline__ uint32_t smem_u32(const void* p) {
    uint32_t a;
    asm("{ .reg .u64 t; cvta.to.shared.u64 t, %1; cvt.u32.u64 %0, t; }" : "=r"(a) : "l"(p));
    return a;
}
__device__ __forceinline__ uint32_t swz(uint32_t off) { return off ^ ((off >> 3) & 0x70); }
__device__ __forceinline__ void ldsm4(uint32_t* r, uint32_t addr) {
    asm volatile("ldmatrix.sync.aligned.m8n8.x4.shared.b16 {%0,%1,%2,%3}, [%4];"
                 : "=r"(r[0]), "=r"(r[1]), "=r"(r[2]), "=r"(r[3]) : "r"(addr));
}
__device__ __forceinline__ void mma16816(float* d, const uint32_t* a, const uint32_t* b) {
    asm volatile("mma.sync.aligned.m16n8k16.row.col.f32.f16.f16.f32 "
                 "{%0,%1,%2,%3}, {%4,%5,%6,%7}, {%8,%9}, {%0,%1,%2,%3};"
                 : "+f"(d[0]), "+f"(d[1]), "+f"(d[2]), "+f"(d[3])
                 : "r"(a[0]), "r"(a[1]), "r"(a[2]), "r"(a[3]), "r"(b[0]), "r"(b[1]));
}
__device__ __forceinline__ void cpa16(uint32_t dst, const void* src) {
    asm volatile("cp.async.cg.shared.global [%0], [%1], 16;" :: "r"(dst), "l"(src));
}

// ================= launch 0: weight synthesis W[OC][IC][9] =================
__global__ void k_weights(const float* __restrict__ fil0, const float* __restrict__ fil1,
                          const float* __restrict__ fil2, const float* __restrict__ w00,
                          const float* __restrict__ w01, const float* __restrict__ w10,
                          const float* __restrict__ w11) {
    int idx = blockIdx.x * blockDim.x + threadIdx.x;
    if (idx >= COUT * CIN) return;
    int OC = idx / CIN, IC = idx % CIN;
    float acc[9];
#pragma unroll
    for (int t = 0; t < 9; t++) acc[t] = 0.f;
    if (OC < 64) {
        if (IC < 64) {
            for (int k = 0; k < 3; k++) {
                float c = w00[(OC * 64 + IC) * 3 + k];
#pragma unroll
                for (int t = 0; t < 9; t++) acc[t] += c * fil0[k * 9 + t];
            }
        } else {
            int ici = (IC - 64) >> 1, tin = (IC - 64) & 1;
            for (int k = 0; k < 6; k++) {
                float c = w10[(OC * 64 + ici) * 6 + k];
#pragma unroll
                for (int t = 0; t < 9; t++) acc[t] += c * fil1[(k * 9 + t) * 2 + tin];
            }
        }
    } else {
        int oco = (OC - 64) >> 1, tout = (OC - 64) & 1;
        if (IC < 64) {
            for (int k = 0; k < 6; k++) {
                float c = w01[(oco * 64 + IC) * 6 + k];
#pragma unroll
                for (int t = 0; t < 9; t++) acc[t] += c * fil1[(k * 9 + t) * 2 + tout];
            }
        } else {
            int ici = (IC - 64) >> 1, tin = (IC - 64) & 1;
            for (int k = 0; k < 12; k++) {
                float c = w11[(oco * 64 + ici) * 12 + k];
#pragma unroll
                for (int t = 0; t < 9; t++) acc[t] += c * fil2[((k * 9 + t) * 2 + tin) * 2 + tout];
            }
        }
    }
#pragma unroll
    for (int t = 0; t < 9; t++) g_W[idx * 9 + t] = acc[t];
}

// ================= launch 1: x -> pixel-major fp16 hi/lo planes + channel means =================
#define XS 36   // smem row stride in words (144 B, keeps uint4 aligned)
__global__ void k_xpack(const float* __restrict__ x0, const float* __restrict__ x1) {
    if (blockIdx.y == 3) {
        if (blockIdx.x >= CIN) return;
        __shared__ float sm[128];
        int ch = blockIdx.x;
        float s = 0.f;
        if (ch < 64) {
            const float* p = x0 + (size_t)ch * NPIX;
            for (int i = threadIdx.x; i < NPIX; i += 128) s += p[i];
        } else {
            int j = ch - 64;
            const float* p = x1 + (size_t)(j >> 1) * (2 * NPIX) + (j & 1);
            for (int i = threadIdx.x; i < NPIX; i += 128) s += p[2 * i];
        }
        sm[threadIdx.x] = s;
        __syncthreads();
        for (int o = 64; o > 0; o >>= 1) {
            if (threadIdx.x < o) sm[threadIdx.x] += sm[threadIdx.x + o];
            __syncthreads();
        }
        if (threadIdx.x == 0) g_meanin[ch] = sm[0] * (1.f / NPIX);
        return;
    }
    __shared__ uint32_t shh[128 * XS];
    __shared__ uint32_t shl[128 * XS];
    const int c = blockIdx.y, tid = threadIdx.x;
    const int px = blockIdx.x * 128 + tid;
#pragma unroll 4
    for (int k2 = 0; k2 < 32; k2++) {
        float v0, v1;
        if (c == 0) {
            v0 = x0[(size_t)(2 * k2) * NPIX + px];
            v1 = x0[(size_t)(2 * k2 + 1) * NPIX + px];
        } else {
            int j = (c - 1) * 64 + 2 * k2;
            float2 p = *(const float2*)&x1[((size_t)(j >> 1) * NPIX + px) * 2];
            v0 = p.x; v1 = p.y;
        }
        __half h0 = __float2half_rn(v0), h1 = __float2half_rn(v1);
        float r0 = v0 - __half2float(h0), r1 = v1 - __half2float(h1);
        __half l0 = __float2half_rn(r0), l1 = __float2half_rn(r1);
        shh[tid * XS + k2] = (uint32_t)__half_as_ushort(h0) | ((uint32_t)__half_as_ushort(h1) << 16);
        shl[tid * XS + k2] = (uint32_t)__half_as_ushort(l0) | ((uint32_t)__half_as_ushort(l1) << 16);
    }
    __syncthreads();
#pragma unroll
    for (int r = 0; r < 8; r++) {
        int s = tid + 128 * r;
        int pl = s >> 3, q = s & 7;
        uint4 vh = *(const uint4*)&shh[pl * XS + q * 4];
        uint4 vl = *(const uint4*)&shl[pl * XS + q * 4];
        size_t o = ((size_t)c * NPIX + blockIdx.x * 128 + pl) * 32 + q * 4;
        *(uint4*)&g_xh[o] = vh;
        *(uint4*)&g_xl[o] = vl;
    }
}

// ================= launch 2: W -> fp16 swizzled half-N tiles + per-OC const =================
__global__ void k_wsplit_addconst(const float* __restrict__ b0, const float* __restrict__ b1) {
    int bid = blockIdx.x, tid = threadIdx.x;
    if (bid < NCHUNK * COUT) {
        if (tid >= 64) return;
        int tile = bid % NCHUNK, n = bid / NCHUNK;
        int tap = tile / 3, c = tile % 3;
        float v = g_W[(n * CIN + c * 64 + tid) * 9 + tap];
        int nh = n / 96, np = n % 96;
        uint32_t sw = swz((uint32_t)(np * 128 + tid * 2));
        g_Wh[(size_t)(tile * 2 + nh) * 6144 + (sw >> 1)] = __float2half_rn(v);
        return;
    }
    __shared__ float sm[256];
    int OC = bid - NCHUNK * COUT;
    float s = 0.f;
    if (tid < CIN) {
        const float* w = &g_W[(OC * CIN + tid) * 9];
        float ws = 0.f;
#pragma unroll
        for (int t = 0; t < 9; t++) ws += w[t];
        s = ws * g_meanin[tid];
    }
    sm[tid] = s;
    __syncthreads();
    for (int o = 128; o > 0; o >>= 1) {
        if (tid < o) sm[tid] += sm[tid + o];
        __syncthreads();
    }
    if (tid == 0) g_add[OC] = (OC < 64) ? b0[OC] : sm[0] * b1[(OC - 64) >> 1];
}

// ================= launch 3: conv = implicit GEMM, fp16 2-term, N=96/CTA =================
// 1024 CTAs (512 px-tiles x 2 n-halves), 256 thr = 8 warps (4M x 2N), 2 CTAs/SM.
__global__ __launch_bounds__(256, 2) void k_conv(float* __restrict__ out) {
    extern __shared__ __align__(1024) char smem[];
    const uint32_t sb = smem_u32(smem);
    const int tid = threadIdx.x;
    const int lane = tid & 31, warp = tid >> 5;
    const int wm = warp & 3, wn = warp >> 2;
    const int nh = blockIdx.x & 1;
    const int pxt = blockIdx.x >> 1;
    const int y = pxt >> 1, xb = (pxt & 1) << 7;

    const int a_row = (lane & 7) + ((lane >> 3) & 1) * 8;
    const int a_ks  = lane >> 4;
    const int b_row = (lane & 7) + ((lane >> 4) << 3);
    const int b_ks  = (lane >> 3) & 1;

    const int am = tid >> 1;         // A row loaded by this thread (0..127)
    const int aq = (tid & 1) * 4;    // first 16B chunk (0 or 4)

    float acc[2][6][4];
#pragma unroll
    for (int t = 0; t < 2; t++)
#pragma unroll
        for (int g = 0; g < 6; g++)
#pragma unroll
            for (int q = 0; q < 4; q++) acc[t][g][q] = 0.f;

#define ISSUE(I, S)                                                                  \
    {                                                                                \
        int tap = (I) / 3, c = (I) % 3;                                              \
        int ky = tap / 3, kx = tap % 3;                                              \
        int ps = (((y + ky + 255) & 255) << 8) | ((xb + am + kx + 255) & 255);       \
        size_t so = ((size_t)((c << 16) + ps)) * 128 + (size_t)(aq * 16);            \
        _Pragma("unroll")                                                            \
        for (int j = 0; j < 4; j++) {                                                \
            uint32_t d = sb + (S) * STG + swz((uint32_t)(am * 128 + (aq + j) * 16)); \
            cpa16(d, (const char*)g_xh + so + j * 16);                               \
            cpa16(d + 16384, (const char*)g_xl + so + j * 16);                       \
        }                                                                            \
        const char* bs = (const char*)g_Wh + (size_t)((I) * 2 + nh) * 12288;         \
        _Pragma("unroll")                                                            \
        for (int j = 0; j < 3; j++) {                                                \
            int off = (tid + 256 * j) * 16;                                          \
            cpa16(sb + (S) * STG + 32768 + off, bs + off);                           \
        }                                                                            \
        asm volatile("cp.async.commit_group;");                                      \
    }

    ISSUE(0, 0);
    asm volatile("cp.async.wait_group 0;");
    __syncthreads();

    for (int i = 0; i < NCHUNK; i++) {
        const int cur = i & 1;
        if (i < NCHUNK - 1) ISSUE(i + 1, cur ^ 1);

        const uint32_t Ab = sb + cur * STG;
        const uint32_t Bb = Ab + 32768;
#pragma unroll
        for (int ks = 0; ks < 4; ks++) {
            uint32_t ah[2][4], al[2][4];
#pragma unroll
            for (int t = 0; t < 2; t++) {
                uint32_t off = swz((uint32_t)((wm * 32 + t * 16 + a_row) * 128 + ks * 32 + a_ks * 16));
                ldsm4(ah[t], Ab + off);
                ldsm4(al[t], Ab + 16384 + off);
            }
#pragma unroll
            for (int g = 0; g < 3; g++) {
                uint32_t offb = swz((uint32_t)((wn * 48 + g * 16 + b_row) * 128 + ks * 32 + b_ks * 16));
                uint32_t bh[4];
                ldsm4(bh, Bb + offb);
#pragma unroll
                for (int t = 0; t < 2; t++) {
#pragma unroll
                    for (int h = 0; h < 2; h++) {
                        float* d = acc[t][g * 2 + h];
                        mma16816(d, ah[t], bh + 2 * h);
                        mma16816(d, al[t], bh + 2 * h);
                    }
                }
            }
        }

        if (i < NCHUNK - 1) {
            asm volatile("cp.async.wait_group 0;");
            __syncthreads();
        }
    }
#undef ISSUE

    // ---- epilogue ----
    const int col = (lane & 3) * 2;
    const int rowq = lane >> 2;
#pragma unroll
    for (int t = 0; t < 2; t++) {
        int px0 = xb + wm * 32 + t * 16 + rowq;
        int px1 = px0 + 8;
#pragma unroll
        for (int nf = 0; nf < 6; nf++) {
            int n = nh * 96 + wn * 48 + nf * 8 + col;
            float g0 = __ldg(&g_add[n]), g1 = __ldg(&g_add[n + 1]);
            float v0 = acc[t][nf][0] + g0, v1 = acc[t][nf][1] + g1;
            float v2 = acc[t][nf][2] + g0, v3 = acc[t][nf][3] + g1;
            if (n < 64) {
                out[(size_t)n * NPIX + y * NN + px0]       = v0;
                out[(size_t)(n + 1) * NPIX + y * NN + px0] = v1;
                out[(size_t)n * NPIX + y * NN + px1]       = v2;
                out[(size_t)(n + 1) * NPIX + y * NN + px1] = v3;
            } else {
                int oco = (n - 64) >> 1;
                size_t base = (size_t)64 * NPIX + ((size_t)(oco * NN + y) * NN) * 2;
                *(float2*)&out[base + px0 * 2] = make_float2(v0, v1);
                *(float2*)&out[base + px1 * 2] = make_float2(v2, v3);
            }
        }
    }
}

// ---------------- launcher ----------------
extern "C" void kernel_launch(void* const* d_in, const int* in_sizes, int n_in,
                              void* d_out, int out_size) {
    const float* x0   = (const float*)d_in[0];
    const float* x1   = (const float*)d_in[1];
    const float* fil0 = (const float*)d_in[2];
    const float* fil1 = (const float*)d_in[3];
    const float* fil2 = (const float*)d_in[4];
    const float* w00  = (const float*)d_in[5];
    const float* w01  = (const float*)d_in[6];
    const float* w10  = (const float*)d_in[7];
    const float* w11  = (const float*)d_in[8];
    const float* b0   = (const float*)d_in[9];
    const float* b1   = (const float*)d_in[10];
    float* out = (float*)d_out;

    k_weights<<<(COUT * CIN + 255) / 256, 256>>>(fil0, fil1, fil2, w00, w01, w10, w11);
    k_xpack<<<dim3(512, 4), 128>>>(x0, x1);
    k_wsplit_addconst<<<NCHUNK * COUT + COUT, 256>>>(b0, b1);

    const int dyn_smem = 2 * STG;  // 90112
    cudaFuncSetAttribute(k_conv, cudaFuncAttributeMaxDynamicSharedMemorySize, dyn_smem);
    k_conv<<<1024, 256, dyn_smem>>>(out);
}

// round 7
// speedup vs baseline: 9.3296x; 1.5060x over previous
#include <cuda_runtime.h>
#include <cuda_fp16.h>
#include <cstdint>

#define NN     256
#define NPIX   65536
#define CIN    192
#define COUT   192
#define NCHUNK 27
#define STG    40960          // stage: A 16K | B 24K

// ---------------- device scratch ----------------
__device__ float g_W[COUT * CIN * 9];
__device__ float g_meanin[CIN];
__device__ float g_add[COUT];
__device__ __align__(1024) __half g_Wh[(size_t)NCHUNK * 12288];  // [chunk] 192x64 fp16 swizzled
__device__ __align__(16) uint32_t g_xh[(size_t)3 * NPIX * 32];   // [c][pix][k2] fp16 pairs

// ---------------- helpers ----------------
__device__ __forceinline__ uint32_t smem_u32(const void* p) {
    uint32_t a;
    asm("{ .reg .u64 t; cvta.to.shared.u64 t, %1; cvt.u32.u64 %0, t; }" : "=r"(a) : "l"(p));
    return a;
}
__device__ __forceinline__ uint32_t swz(uint32_t off) { return off ^ ((off >> 3) & 0x70); }
__device__ __forceinline__ void ldsm4(uint32_t* r, uint32_t addr) {
    asm volatile("ldmatrix.sync.aligned.m8n8.x4.shared.b16 {%0,%1,%2,%3}, [%4];"
                 : "=r"(r[0]), "=r"(r[1]), "=r"(r[2]), "=r"(r[3]) : "r"(addr));
}
__device__ __forceinline__ void mma16816(float* d, const uint32_t* a, const uint32_t* b) {
    asm volatile("mma.sync.aligned.m16n8k16.row.col.f32.f16.f16.f32 "
                 "{%0,%1,%2,%3}, {%4,%5,%6,%7}, {%8,%9}, {%0,%1,%2,%3};"
                 : "+f"(d[0]), "+f"(d[1]), "+f"(d[2]), "+f"(d[3])
                 : "r"(a[0]), "r"(a[1]), "r"(a[2]), "r"(a[3]), "r"(b[0]), "r"(b[1]));
}
__device__ __forceinline__ void cpa16(uint32_t dst, const void* src) {
    asm volatile("cp.async.cg.shared.global [%0], [%1], 16;" :: "r"(dst), "l"(src));
}

// ================= launch 0: weight synthesis W[OC][IC][9] =================
__global__ void k_weights(const float* __restrict__ fil0, const float* __restrict__ fil1,
                          const float* __restrict__ fil2, const float* __restrict__ w00,
                          const float* __restrict__ w01, const float* __restrict__ w10,
                          const float* __restrict__ w11) {
    int idx = blockIdx.x * blockDim.x + threadIdx.x;
    if (idx >= COUT * CIN) return;
    int OC = idx / CIN, IC = idx % CIN;
    float acc[9];
#pragma unroll
    for (int t = 0; t < 9; t++) acc[t] = 0.f;
    if (OC < 64) {
        if (IC < 64) {
            for (int k = 0; k < 3; k++) {
                float c = w00[(OC * 64 + IC) * 3 + k];
#pragma unroll
                for (int t = 0; t < 9; t++) acc[t] += c * fil0[k * 9 + t];
            }
        } else {
            int ici = (IC - 64) >> 1, tin = (IC - 64) & 1;
            for (int k = 0; k < 6; k++) {
                float c = w10[(OC * 64 + ici) * 6 + k];
#pragma unroll
                for (int t = 0; t < 9; t++) acc[t] += c * fil1[(k * 9 + t) * 2 + tin];
            }
        }
    } else {
        int oco = (OC - 64) >> 1, tout = (OC - 64) & 1;
        if (IC < 64) {
            for (int k = 0; k < 6; k++) {
                float c = w01[(oco * 64 + IC) * 6 + k];
#pragma unroll
                for (int t = 0; t < 9; t++) acc[t] += c * fil1[(k * 9 + t) * 2 + tout];
            }
        } else {
            int ici = (IC - 64) >> 1, tin = (IC - 64) & 1;
            for (int k = 0; k < 12; k++) {
                float c = w11[(oco * 64 + ici) * 12 + k];
#pragma unroll
                for (int t = 0; t < 9; t++) acc[t] += c * fil2[((k * 9 + t) * 2 + tin) * 2 + tout];
            }
        }
    }
#pragma unroll
    for (int t = 0; t < 9; t++) g_W[idx * 9 + t] = acc[t];
}

// ================= launch 1: x -> pixel-major fp16 planes + channel means =================
#define XS 36   // smem row stride in words (144 B, keeps uint4 aligned)
__global__ void k_xpack(const float* __restrict__ x0, const float* __restrict__ x1) {
    if (blockIdx.y == 3) {
        if (blockIdx.x >= CIN) return;
        __shared__ float sm[128];
        int ch = blockIdx.x;
        float s = 0.f;
        if (ch < 64) {
            const float* p = x0 + (size_t)ch * NPIX;
            for (int i = threadIdx.x; i < NPIX; i += 128) s += p[i];
        } else {
            int j = ch - 64;
            const float* p = x1 + (size_t)(j >> 1) * (2 * NPIX) + (j & 1);
            for (int i = threadIdx.x; i < NPIX; i += 128) s += p[2 * i];
        }
        sm[threadIdx.x] = s;
        __syncthreads();
        for (int o = 64; o > 0; o >>= 1) {
            if (threadIdx.x < o) sm[threadIdx.x] += sm[threadIdx.x + o];
            __syncthreads();
        }
        if (threadIdx.x == 0) g_meanin[ch] = sm[0] * (1.f / NPIX);
        return;
    }
    __shared__ uint32_t shh[128 * XS];
    const int c = blockIdx.y, tid = threadIdx.x;
    const int px = blockIdx.x * 128 + tid;
#pragma unroll 4
    for (int k2 = 0; k2 < 32; k2++) {
        float v0, v1;
        if (c == 0) {
            v0 = x0[(size_t)(2 * k2) * NPIX + px];
            v1 = x0[(size_t)(2 * k2 + 1) * NPIX + px];
        } else {
            int j = (c - 1) * 64 + 2 * k2;
            float2 p = *(const float2*)&x1[((size_t)(j >> 1) * NPIX + px) * 2];
            v0 = p.x; v1 = p.y;
        }
        __half h0 = __float2half_rn(v0), h1 = __float2half_rn(v1);
        shh[tid * XS + k2] = (uint32_t)__half_as_ushort(h0) | ((uint32_t)__half_as_ushort(h1) << 16);
    }
    __syncthreads();
#pragma unroll
    for (int r = 0; r < 8; r++) {
        int s = tid + 128 * r;
        int pl = s >> 3, q = s & 7;
        uint4 vh = *(const uint4*)&shh[pl * XS + q * 4];
        size_t o = ((size_t)c * NPIX + blockIdx.x * 128 + pl) * 32 + q * 4;
        *(uint4*)&g_xh[o] = vh;
    }
}

// ================= launch 2: W -> fp16 swizzled tiles + per-OC const =================
__global__ void k_wsplit_addconst(const float* __restrict__ b0, const float* __restrict__ b1) {
    int bid = blockIdx.x, tid = threadIdx.x;
    if (bid < NCHUNK * COUT) {
        if (tid >= 64) return;
        int tile = bid % NCHUNK, n = bid / NCHUNK;
        int tap = tile / 3, c = tile % 3;
        float v = g_W[(n * CIN + c * 64 + tid) * 9 + tap];
        uint32_t sw = swz((uint32_t)(n * 128 + tid * 2));
        g_Wh[(size_t)tile * 12288 + (sw >> 1)] = __float2half_rn(v);
        return;
    }
    __shared__ float sm[256];
    int OC = bid - NCHUNK * COUT;
    float s = 0.f;
    if (tid < CIN) {
        const float* w = &g_W[(OC * CIN + tid) * 9];
        float ws = 0.f;
#pragma unroll
        for (int t = 0; t < 9; t++) ws += w[t];
        s = ws * g_meanin[tid];
    }
    sm[tid] = s;
    __syncthreads();
    for (int o = 128; o > 0; o >>= 1) {
        if (tid < o) sm[tid] += sm[tid + o];
        __syncthreads();
    }
    if (tid == 0) g_add[OC] = (OC < 64) ? b0[OC] : sm[0] * b1[(OC - 64) >> 1];
}

// ================= launch 3: conv = implicit GEMM, 1-term fp16, N=192/CTA =================
// 512 CTAs (one per 128-px tile), 256 thr = 8 warps (4M x 2N), 2 CTAs/SM.
__global__ __launch_bounds__(256, 2) void k_conv(float* __restrict__ out) {
    extern __shared__ __align__(1024) char smem[];
    const uint32_t sb = smem_u32(smem);
    const int tid = threadIdx.x;
    const int lane = tid & 31, warp = tid >> 5;
    const int wm = warp & 3, wn = warp >> 2;
    const int y = blockIdx.x >> 1, xb = (blockIdx.x & 1) << 7;

    const int a_row = (lane & 7) + ((lane >> 3) & 1) * 8;
    const int a_ks  = lane >> 4;
    const int b_row = (lane & 7) + ((lane >> 4) << 3);
    const int b_ks  = (lane >> 3) & 1;

    const int am = tid >> 1;         // A row loaded by this thread (0..127)
    const int aq = (tid & 1) * 4;    // first 16B chunk (0 or 4)

    float acc[2][12][4];
#pragma unroll
    for (int t = 0; t < 2; t++)
#pragma unroll
        for (int g = 0; g < 12; g++)
#pragma unroll
            for (int q = 0; q < 4; q++) acc[t][g][q] = 0.f;

#define ISSUE(I, S)                                                                  \
    {                                                                                \
        int tap = (I) / 3, c = (I) % 3;                                              \
        int ky = tap / 3, kx = tap % 3;                                              \
        int ps = (((y + ky + 255) & 255) << 8) | ((xb + am + kx + 255) & 255);       \
        size_t so = ((size_t)((c << 16) + ps)) * 128 + (size_t)(aq * 16);            \
        _Pragma("unroll")                                                            \
        for (int j = 0; j < 4; j++) {                                                \
            uint32_t d = sb + (S) * STG + swz((uint32_t)(am * 128 + (aq + j) * 16)); \
            cpa16(d, (const char*)g_xh + so + j * 16);                               \
        }                                                                            \
        const char* bs = (const char*)g_Wh + (size_t)(I) * 24576;                    \
        _Pragma("unroll")                                                            \
        for (int j = 0; j < 6; j++) {                                                \
            int off = (tid + 256 * j) * 16;                                          \
            cpa16(sb + (S) * STG + 16384 + off, bs + off);                           \
        }                                                                            \
        asm volatile("cp.async.commit_group;");                                      \
    }

    ISSUE(0, 0);
    asm volatile("cp.async.wait_group 0;");
    __syncthreads();

    for (int i = 0; i < NCHUNK; i++) {
        const int cur = i & 1;
        if (i < NCHUNK - 1) ISSUE(i + 1, cur ^ 1);

        const uint32_t Ab = sb + cur * STG;
        const uint32_t Bb = Ab + 16384;
#pragma unroll
        for (int ks = 0; ks < 4; ks++) {
            uint32_t ah[2][4];
#pragma unroll
            for (int t = 0; t < 2; t++) {
                uint32_t off = swz((uint32_t)((wm * 32 + t * 16 + a_row) * 128 + ks * 32 + a_ks * 16));
                ldsm4(ah[t], Ab + off);
            }
#pragma unroll
            for (int g = 0; g < 6; g++) {
                uint32_t offb = swz((uint32_t)((wn * 96 + g * 16 + b_row) * 128 + ks * 32 + b_ks * 16));
                uint32_t bh[4];
                ldsm4(bh, Bb + offb);
#pragma unroll
                for (int t = 0; t < 2; t++) {
#pragma unroll
                    for (int h = 0; h < 2; h++) {
                        mma16816(acc[t][g * 2 + h], ah[t], bh + 2 * h);
                    }
                }
            }
        }

        if (i < NCHUNK - 1) {
            asm volatile("cp.async.wait_group 0;");
            __syncthreads();
        }
    }
#undef ISSUE

    // ---- epilogue ----
    const int col = (lane & 3) * 2;
    const int rowq = lane >> 2;
#pragma unroll
    for (int t = 0; t < 2; t++) {
        int px0 = xb + wm * 32 + t * 16 + rowq;
        int px1 = px0 + 8;
#pragma unroll
        for (int nf = 0; nf < 12; nf++) {
            int n = wn * 96 + nf * 8 + col;
            float g0 = __ldg(&g_add[n]), g1 = __ldg(&g_add[n + 1]);
            float v0 = acc[t][nf][0] + g0, v1 = acc[t][nf][1] + g1;
            float v2 = acc[t][nf][2] + g0, v3 = acc[t][nf][3] + g1;
            if (n < 64) {
                out[(size_t)n * NPIX + y * NN + px0]       = v0;
                out[(size_t)(n + 1) * NPIX + y * NN + px0] = v1;
                out[(size_t)n * NPIX + y * NN + px1]       = v2;
                out[(size_t)(n + 1) * NPIX + y * NN + px1] = v3;
            } else {
                int oco = (n - 64) >> 1;
                size_t base = (size_t)64 * NPIX + ((size_t)(oco * NN + y) * NN) * 2;
                *(float2*)&out[base + px0 * 2] = make_float2(v0, v1);
                *(float2*)&out[base + px1 * 2] = make_float2(v2, v3);
            }
        }
    }
}

// ---------------- launcher ----------------
extern "C" void kernel_launch(void* const* d_in, const int* in_sizes, int n_in,
                              void* d_out, int out_size) {
    const float* x0   = (const float*)d_in[0];
    const float* x1   = (const float*)d_in[1];
    const float* fil0 = (const float*)d_in[2];
    const float* fil1 = (const float*)d_in[3];
    const float* fil2 = (const float*)d_in[4];
    const float* w00  = (const float*)d_in[5];
    const float* w01  = (const float*)d_in[6];
    const float* w10  = (const float*)d_in[7];
    const float* w11  = (const float*)d_in[8];
    const float* b0   = (const float*)d_in[9];
    const float* b1   = (const float*)d_in[10];
    float* out = (float*)d_out;

    k_weights<<<(COUT * CIN + 255) / 256, 256>>>(fil0, fil1, fil2, w00, w01, w10, w11);
    k_xpack<<<dim3(512, 4), 128>>>(x0, x1);
    k_wsplit_addconst<<<NCHUNK * COUT + COUT, 256>>>(b0, b1);

    const int dyn_smem = 2 * STG;  // 81920
    cudaFuncSetAttribute(k_conv, cudaFuncAttributeMaxDynamicSharedMemorySize, dyn_smem);
    k_conv<<<512, 256, dyn_smem>>>(out);
}